// round 1
// baseline (speedup 1.0000x reference)
#include <cuda_runtime.h>
#include <math.h>

// Persistent scratch: mask flags for up to 4096 time steps (T=512 here).
__device__ unsigned char g_mask_flags[4096];

// Kernel 1: compute mask by ranking each random value (O(T^2), one block).
// mask[t] = (#{j : rv[j] < rv[t]  or (rv[j]==rv[t] and j<t)} < n_mask)
__global__ void __launch_bounds__(1024)
mask_rank_kernel(const float* __restrict__ rv, float* __restrict__ out_mask,
                 int T, int n_mask) {
    __shared__ float s[4096];
    for (int j = threadIdx.x; j < T; j += blockDim.x) s[j] = rv[j];
    __syncthreads();
    for (int t = threadIdx.x; t < T; t += blockDim.x) {
        float v = s[t];
        int r = 0;
        for (int j = 0; j < T; j++) {
            float u = s[j];
            r += (u < v) || (u == v && j < t);
        }
        unsigned char m = (r < n_mask) ? 1 : 0;
        g_mask_flags[t] = m;
        out_mask[t] = m ? 1.0f : 0.0f;
    }
}

// Kernel 2: masked fill of the 3 tensors, vectorized float4.
// F/4 float4 per time-step row; F=256 -> 64 vecs per t, so the mask is
// warp-uniform and the load-skip branch has zero divergence.
__global__ void __launch_bounds__(256)
apply_mask_kernel(const float4* __restrict__ a,
                  const float4* __restrict__ b,
                  const float4* __restrict__ c,
                  float4* __restrict__ oa,
                  float4* __restrict__ ob,
                  float4* __restrict__ oc,
                  int vecN, int fvec, int T) {
    int i = blockIdx.x * blockDim.x + threadIdx.x;
    if (i >= vecN) return;
    int t = (i / fvec) % T;
    if (g_mask_flags[t]) {
        float4 z = make_float4(0.f, 0.f, 0.f, 0.f);
        oa[i] = z; ob[i] = z; oc[i] = z;
    } else {
        oa[i] = a[i]; ob[i] = b[i]; oc[i] = c[i];
    }
}

extern "C" void kernel_launch(void* const* d_in, const int* in_sizes, int n_in,
                              void* d_out, int out_size) {
    const float* x_tre = (const float*)d_in[0];
    const float* x_sea = (const float*)d_in[1];
    const float* x_res = (const float*)d_in[2];
    const float* rv    = (const float*)d_in[3];

    const int N = in_sizes[0];      // B*T*F elements per tensor
    const int T = in_sizes[3];      // time steps
    // Layout from reference shapes: (B, T, F) with F the fastest dim.
    // N = B*T*F and the total element count gives us F implicitly:
    // out = [z_tre(N), z_sea(N), z_res(N), mask(T)]
    // F = 256 for this problem; derive robustly: N / (B*T). B unknown, but
    // we only need F. Reference fixes F=256; recover it if divisible.
    int F = 256;
    if (N % T == 0) {
        // N/T = B*F; F is the innermost 256 in this dataset. Keep 256 unless
        // it doesn't divide.
        if ((N / T) % 256 != 0) F = N / T; // degenerate fallback (B==1)
    }

    float* out = (float*)d_out;
    float* z_tre = out;
    float* z_sea = out + (size_t)N;
    float* z_res = out + (size_t)2 * N;
    float* out_mask = out + (size_t)3 * N;

    int n_mask = (int)ceil((double)T * 0.4);

    mask_rank_kernel<<<1, (T < 1024 ? ((T + 31) / 32) * 32 : 1024)>>>(
        rv, out_mask, T, n_mask);

    int vecN = N / 4;
    int fvec = F / 4;
    int threads = 256;
    int blocks = (vecN + threads - 1) / threads;
    apply_mask_kernel<<<blocks, threads>>>(
        (const float4*)x_tre, (const float4*)x_sea, (const float4*)x_res,
        (float4*)z_tre, (float4*)z_sea, (float4*)z_res,
        vecN, fvec, T);
}

// round 2
// speedup vs baseline: 1.2614x; 1.2614x over previous
#include <cuda_runtime.h>
#include <math.h>

// Fused kernel: each block (a) stages rv[0..T) in shared, (b) computes the
// rank-based mask flags for ONLY the ~4-5 time-steps its float4 range covers
// (warp-parallel, ~60 cycles), (c) block 0 additionally writes the full
// T-float mask output, (d) does the streaming masked copy/fill.
//
// mask[t] = rank(rv[t]) < n_mask, rank = #{j: rv[j]<rv[t] or (rv[j]==rv[t] && j<t)}
// which exactly reproduces argsort(rv)[:n_mask] (stable tie-break).
__global__ void __launch_bounds__(256)
fused_mask_kernel(const float4* __restrict__ a,
                  const float4* __restrict__ b,
                  const float4* __restrict__ c,
                  const float*  __restrict__ rv,
                  float4* __restrict__ oa,
                  float4* __restrict__ ob,
                  float4* __restrict__ oc,
                  float*  __restrict__ out_mask,
                  int vecN, int fvec, int T, int n_mask) {
    extern __shared__ float srv[];              // T floats of rv
    __shared__ unsigned char s_flag[256];       // per-row mask flags for this block

    const int tid = threadIdx.x;

    // Stage rv into shared (T*4 bytes; hits L2 after first wave).
    for (int j = tid; j < T; j += blockDim.x) srv[j] = rv[j];
    __syncthreads();

    const long long blockStart = (long long)blockIdx.x * blockDim.x;
    const int i = (int)(blockStart + tid);

    // Rows (time-steps) covered by this block's float4 range.
    const int r0 = (int)(blockStart / fvec);
    long long lastIdx = blockStart + blockDim.x - 1;
    if (lastIdx >= vecN) lastIdx = vecN - 1;
    const int r1 = (lastIdx >= blockStart) ? (int)(lastIdx / fvec) : r0;
    const int nrows = r1 - r0 + 1;              // <= 5 when fvec >= 64

    const int wid  = tid >> 5;
    const int lane = tid & 31;

    // Warp-parallel rank per covered row.
    for (int w = wid; w < nrows && w < 256; w += (int)(blockDim.x >> 5)) {
        const int t = (r0 + w) % T;
        const float v = srv[t];
        int cnt = 0;
        for (int j = lane; j < T; j += 32) {
            const float u = srv[j];
            cnt += (u < v) || (u == v && j < t);
        }
        #pragma unroll
        for (int off = 16; off; off >>= 1)
            cnt += __shfl_down_sync(0xffffffffu, cnt, off);
        if (lane == 0) s_flag[w] = (cnt < n_mask) ? 1 : 0;
    }

    // Block 0 owns the mask output (overlapped with other blocks' traffic).
    if (blockIdx.x == 0) {
        for (int t = tid; t < T; t += blockDim.x) {
            const float v = srv[t];
            int cnt = 0;
            for (int j = 0; j < T; j++) {
                const float u = srv[j];
                cnt += (u < v) || (u == v && j < t);
            }
            out_mask[t] = (cnt < n_mask) ? 1.0f : 0.0f;
        }
    }
    __syncthreads();

    if (i >= vecN) return;
    const int row = i / fvec;
    if (s_flag[row - r0]) {
        const float4 z = make_float4(0.f, 0.f, 0.f, 0.f);
        oa[i] = z; ob[i] = z; oc[i] = z;
    } else {
        oa[i] = a[i]; ob[i] = b[i]; oc[i] = c[i];
    }
}

extern "C" void kernel_launch(void* const* d_in, const int* in_sizes, int n_in,
                              void* d_out, int out_size) {
    const float* x_tre = (const float*)d_in[0];
    const float* x_sea = (const float*)d_in[1];
    const float* x_res = (const float*)d_in[2];
    const float* rv    = (const float*)d_in[3];

    const int N = in_sizes[0];      // B*T*F elements per tensor
    const int T = in_sizes[3];      // time steps

    int F = 256;
    if (N % T == 0 && (N / T) % 256 != 0) F = N / T;  // degenerate fallback

    float* out = (float*)d_out;
    float* z_tre    = out;
    float* z_sea    = out + (size_t)N;
    float* z_res    = out + (size_t)2 * N;
    float* out_mask = out + (size_t)3 * N;

    const int n_mask = (int)ceil((double)T * 0.4);
    const int vecN = N / 4;
    const int fvec = F / 4;
    const int threads = 256;
    const int blocks = (vecN + threads - 1) / threads;
    const size_t shmem = (size_t)T * sizeof(float);

    fused_mask_kernel<<<blocks, threads, shmem>>>(
        (const float4*)x_tre, (const float4*)x_sea, (const float4*)x_res, rv,
        (float4*)z_tre, (float4*)z_sea, (float4*)z_res, out_mask,
        vecN, fvec, T, n_mask);
}